// round 11
// baseline (speedup 1.0000x reference)
#include <cuda_runtime.h>
#include <cuda_bf16.h>
#include <cstdint>

#define NFEAT 6272
#define MMEM  50000
#define CDIM  1024
#define BIMG  8
#define FHW   28
#define IMG   224
#define NPIX  (BIMG*IMG*IMG)

#define MTILE 128
#define NTILE 256
#define NTILES 196
#define MPAD2 (NTILES*NTILE)     // 50176
#define KCH   64                 // bf16 elems per K chunk (128B rows)
#define NCHUNKS (CDIM/KCH)       // 16
#define NSTAGE 4
#define NTHREADS 512

// smem rows: 128B data + 16B pad -> conflict-free ldmatrix
#define ROWB    144
#define ASTAGEB (MTILE*ROWB)                 // 18432
#define BSTAGEB (NTILE*ROWB)                 // 36864
#define SBBASE  (NSTAGE*ASTAGEB)             // 73728
#define AUX_OFF (SBBASE + NSTAGE*BSTAGEB)    // 221184
#define SMEM_TOTAL (AUX_OFF + 2048)          // m2s(256f) f2s(128f) sred(128u)

// ---- static device scratch ----
__device__ float g_f2[NFEAT];
__device__ float g_m2[MPAD2];
__device__ unsigned int g_minbits[NFEAT];
__device__ float g_gauss[17];
__device__ float g_resized[NPIX];
__device__ float g_tmpb[NPIX];
__device__ __nv_bfloat16 g_featb[NFEAT*CDIM];
__device__ __nv_bfloat16 g_memb[(size_t)MPAD2*CDIM];

static __device__ __forceinline__ uint32_t smem_u32(const void* p){
    uint32_t a; asm("{ .reg .u64 t; cvta.to.shared.u64 t, %1; cvt.u32.u64 %0, t; }"
                    : "=r"(a) : "l"(p));
    return a;
}
static __device__ __forceinline__ void cp16(uint32_t dst, const void* src){
    asm volatile("cp.async.cg.shared.global [%0], [%1], 16;" :: "r"(dst), "l"(src) : "memory");
}
static __device__ __forceinline__ void ldsm4(uint32_t p, uint32_t &r0, uint32_t &r1,
                                             uint32_t &r2, uint32_t &r3){
    asm volatile("ldmatrix.sync.aligned.m8n8.x4.shared.b16 {%0,%1,%2,%3}, [%4];"
                 : "=r"(r0), "=r"(r1), "=r"(r2), "=r"(r3) : "r"(p));
}
static __device__ __forceinline__ void mma16816(float* c, uint32_t a0, uint32_t a1,
                                                uint32_t a2, uint32_t a3,
                                                uint32_t b0, uint32_t b1){
    asm volatile("mma.sync.aligned.m16n8k16.row.col.f32.bf16.bf16.f32 "
                 "{%0,%1,%2,%3},{%4,%5,%6,%7},{%8,%9},{%0,%1,%2,%3};"
                 : "+f"(c[0]), "+f"(c[1]), "+f"(c[2]), "+f"(c[3])
                 : "r"(a0), "r"(a1), "r"(a2), "r"(a3), "r"(b0), "r"(b1));
}

// ---------------------------------------------------------------------------
__global__ void k_init(){
    int tid = blockIdx.x * blockDim.x + threadIdx.x;
    if (tid < NFEAT) g_minbits[tid] = 0x7F7FFFFFu;
    if (tid < 17){
        float s = 0.f;
        #pragma unroll
        for (int t = 0; t < 17; t++){ float d = (float)t - 8.f; s += expf(-(d*d)/32.f); }
        float d = (float)tid - 8.f;
        g_gauss[tid] = expf(-(d*d)/32.f) / s;
    }
}

// ---------------------------------------------------------------------------
// fused fp32->bf16 conversion + squared row norm. one warp per row.
// ---------------------------------------------------------------------------
__global__ void k_prep(const float* __restrict__ X, int nrows, int nvalid, int mode){
    int warp = (blockIdx.x * blockDim.x + threadIdx.x) >> 5;
    int lane = threadIdx.x & 31;
    if (warp >= nrows) return;
    __nv_bfloat16* dst = (mode == 0 ? g_featb : g_memb) + (size_t)warp * CDIM;
    if (warp >= nvalid){
        uint2 z = make_uint2(0u, 0u);
        #pragma unroll
        for (int j = 0; j < 8; j++) ((uint2*)dst)[j*32 + lane] = z;
        if (lane == 0) g_m2[warp] = __int_as_float(0x7F800000);
        return;
    }
    const float4* src = (const float4*)(X + (size_t)warp * CDIM);
    float s = 0.f;
    #pragma unroll
    for (int j = 0; j < 8; j++){
        float4 v = src[j*32 + lane];
        s += v.x*v.x + v.y*v.y + v.z*v.z + v.w*v.w;
        __nv_bfloat162 p0 = __floats2bfloat162_rn(v.x, v.y);
        __nv_bfloat162 p1 = __floats2bfloat162_rn(v.z, v.w);
        uint2 o; o.x = *(uint32_t*)&p0; o.y = *(uint32_t*)&p1;
        ((uint2*)dst)[j*32 + lane] = o;
    }
    #pragma unroll
    for (int o = 16; o > 0; o >>= 1) s += __shfl_xor_sync(0xFFFFFFFFu, s, o);
    if (lane == 0){ if (mode == 0) g_f2[warp] = s; else g_m2[warp] = s; }
}

// ---------------------------------------------------------------------------
// bf16 HMMA distance GEMM + min epilogue.
// CTA 128x256, 512 threads, 16 warps (2M x 8N), warp tile 64x32.
// KCH=64 (4 k16 steps per barrier region), 4-stage ring, wait_group 1,
// cross-chunk fragment double-buffer. 1 CTA/SM (218KB smem, 64K regs).
// ---------------------------------------------------------------------------
__global__ __launch_bounds__(NTHREADS, 1)
void k_gemm_tc(){
    extern __shared__ char smraw[];
    const uint32_t sbase = smem_u32(smraw);
    const int tid = threadIdx.x;
    const int wid = tid >> 5, lane = tid & 31;
    const int warpM = wid >> 3, warpN = wid & 7;
    const int rowBase = blockIdx.x * MTILE;
    const int colBase = blockIdx.y * NTILE;

    float* m2s = (float*)(smraw + AUX_OFF);
    float* f2s = (float*)(smraw + AUX_OFF + 1024);
    unsigned int* sred = (unsigned int*)(smraw + AUX_OFF + 1536);
    if (tid < NTILE) m2s[tid] = g_m2[colBase + tid];
    if (tid >= NTILE && tid < NTILE + MTILE) f2s[tid - NTILE] = g_f2[rowBase + tid - NTILE];
    if (tid >= NTILE + MTILE && tid < NTILE + 2*MTILE)
        sred[tid - NTILE - MTILE] = 0x7F7FFFFFu;

    // ---- per-thread cp.async endpoints: A rows r,r+64 ; B rows r,r+64,r+128,r+192 ----
    const int r0 = tid >> 3, seg = tid & 7;
    const char* aSrc0 = (const char*)g_featb + ((size_t)(rowBase + r0))*(CDIM*2) + seg*16;
    const char* aSrc1 = aSrc0 + (size_t)64*(CDIM*2);
    const char* bSrc0 = (const char*)g_memb  + ((size_t)(colBase + r0))*(CDIM*2) + seg*16;
    const char* bSrc1 = bSrc0 + (size_t)64*(CDIM*2);
    const char* bSrc2 = bSrc0 + (size_t)128*(CDIM*2);
    const char* bSrc3 = bSrc0 + (size_t)192*(CDIM*2);
    const uint32_t aDst0 = sbase + r0*ROWB + seg*16;
    const uint32_t aDst1 = aDst0 + 64*ROWB;
    const uint32_t bDst0 = sbase + SBBASE + r0*ROWB + seg*16;
    const uint32_t bDst1 = bDst0 + 64*ROWB;
    const uint32_t bDst2 = bDst0 + 128*ROWB;
    const uint32_t bDst3 = bDst0 + 192*ROWB;

    #define ISSUE(ks, st) do { \
        const size_t _ko = (size_t)(ks) * (KCH*2); \
        const uint32_t _ao = (uint32_t)((st) * ASTAGEB); \
        const uint32_t _bo = (uint32_t)((st) * BSTAGEB); \
        cp16(aDst0 + _ao, aSrc0 + _ko); \
        cp16(aDst1 + _ao, aSrc1 + _ko); \
        cp16(bDst0 + _bo, bSrc0 + _ko); \
        cp16(bDst1 + _bo, bSrc1 + _ko); \
        cp16(bDst2 + _bo, bSrc2 + _ko); \
        cp16(bDst3 + _bo, bSrc3 + _ko); \
        asm volatile("cp.async.commit_group;" ::: "memory"); \
    } while(0)

    // ---- LDSM base offsets ----
    const int lrow = lane & 15;
    const int lcol16 = (lane >> 4) & 1;
    const uint32_t aOff = sbase + (warpM*64 + lrow)*ROWB + lcol16*16;
    const uint32_t bOff = sbase + SBBASE + (warpN*32 + lrow)*ROWB + lcol16*16;

    uint32_t fa[2][4][4], fb[2][2][4];
    #define LOAD_FRAGS(buf, ap, bp) do { \
        _Pragma("unroll") \
        for (int mi = 0; mi < 4; mi++) \
            ldsm4((ap) + mi*(16*ROWB), fa[buf][mi][0], fa[buf][mi][1], \
                  fa[buf][mi][2], fa[buf][mi][3]); \
        _Pragma("unroll") \
        for (int nh = 0; nh < 2; nh++) \
            ldsm4((bp) + nh*(16*ROWB), fb[buf][nh][0], fb[buf][nh][1], \
                  fb[buf][nh][2], fb[buf][nh][3]); \
    } while(0)

    #define MMA_STEP(buf) do { \
        _Pragma("unroll") \
        for (int mi = 0; mi < 4; mi++) \
            _Pragma("unroll") \
            for (int ni = 0; ni < 4; ni++){ \
                int nh = ni >> 1, od = ni & 1; \
                mma16816(acc[mi][ni], fa[buf][mi][0], fa[buf][mi][1], \
                         fa[buf][mi][2], fa[buf][mi][3], \
                         fb[buf][nh][od], fb[buf][nh][od + 2]); \
            } \
    } while(0)

    float acc[4][4][4];
    #pragma unroll
    for (int mi = 0; mi < 4; mi++)
        #pragma unroll
        for (int ni = 0; ni < 4; ni++)
            #pragma unroll
            for (int k = 0; k < 4; k++) acc[mi][ni][k] = 0.f;

    // prologue: chunks 0,1,2 in flight; chunks 0,1 resident after wait
    ISSUE(0, 0); ISSUE(1, 1); ISSUE(2, 2);
    asm volatile("cp.async.wait_group 1;" ::: "memory");
    __syncthreads();

    // preload fragments for (chunk 0, step 0) into buf 0
    LOAD_FRAGS(0, aOff, bOff);

    for (int ks4 = 0; ks4 < NCHUNKS; ks4 += 4){
        #pragma unroll
        for (int u = 0; u < 4; u++){
            const int ks = ks4 + u;             // (ks & 3) == u
            if (ks > 0){
                asm volatile("cp.async.wait_group 1;" ::: "memory");
                __syncthreads();
            }
            if (ks + 3 < NCHUNKS) ISSUE(ks + 3, (u + 3) & 3);
            const uint32_t ao = (uint32_t)(u*ASTAGEB);
            const uint32_t bo = (uint32_t)(u*BSTAGEB);
            // 4 k16 steps; frag ping-pong; cross-chunk preload at step 3
            LOAD_FRAGS(1, aOff + ao + 32, bOff + bo + 32);
            MMA_STEP(0);
            LOAD_FRAGS(0, aOff + ao + 64, bOff + bo + 64);
            MMA_STEP(1);
            LOAD_FRAGS(1, aOff + ao + 96, bOff + bo + 96);
            MMA_STEP(0);
            if (ks + 1 < NCHUNKS)
                LOAD_FRAGS(0, aOff + ((u + 1) & 3)*ASTAGEB, bOff + ((u + 1) & 3)*BSTAGEB);
            MMA_STEP(1);
        }
    }
    #undef ISSUE
    #undef LOAD_FRAGS
    #undef MMA_STEP

    // ---- epilogue: d2 = f2 + m2 - 2*dot, min-reduce ----
    {
        const int q = lane >> 2;        // row-in-8 group
        const int ql = lane & 3;        // col pair selector
        float m2v[4][2], f2lo[4], f2hi[4];
        #pragma unroll
        for (int ni = 0; ni < 4; ni++){
            int c = warpN*32 + ni*8 + 2*ql;
            m2v[ni][0] = m2s[c];
            m2v[ni][1] = m2s[c + 1];
        }
        #pragma unroll
        for (int mi = 0; mi < 4; mi++){
            f2lo[mi] = f2s[warpM*64 + mi*16 + q];
            f2hi[mi] = f2s[warpM*64 + mi*16 + q + 8];
        }
        #pragma unroll
        for (int mi = 0; mi < 4; mi++){
            float vlo = __int_as_float(0x7F800000);
            float vhi = vlo;
            #pragma unroll
            for (int ni = 0; ni < 4; ni++){
                vlo = fminf(vlo, fminf(fmaf(-2.f, acc[mi][ni][0], f2lo[mi] + m2v[ni][0]),
                                       fmaf(-2.f, acc[mi][ni][1], f2lo[mi] + m2v[ni][1])));
                vhi = fminf(vhi, fminf(fmaf(-2.f, acc[mi][ni][2], f2hi[mi] + m2v[ni][0]),
                                       fmaf(-2.f, acc[mi][ni][3], f2hi[mi] + m2v[ni][1])));
            }
            #pragma unroll
            for (int o = 1; o < 4; o <<= 1){
                vlo = fminf(vlo, __shfl_xor_sync(0xFFFFFFFFu, vlo, o));
                vhi = fminf(vhi, __shfl_xor_sync(0xFFFFFFFFu, vhi, o));
            }
            if (ql == 0){
                int r = warpM*64 + mi*16 + q;
                atomicMin(&sred[r],     __float_as_uint(fmaxf(vlo, 0.f)));
                atomicMin(&sred[r + 8], __float_as_uint(fmaxf(vhi, 0.f)));
            }
        }
    }
    __syncthreads();
    if (tid < MTILE)
        atomicMin(&g_minbits[rowBase + tid], sred[tid]);
}

// ---------------------------------------------------------------------------
__global__ void k_scores(float* __restrict__ out){
    __shared__ unsigned int red[256];
    const int b = blockIdx.x;
    unsigned int mb = 0u;
    for (int i = threadIdx.x; i < FHW*FHW; i += 256)
        mb = max(mb, g_minbits[b*FHW*FHW + i]);
    red[threadIdx.x] = mb; __syncthreads();
    for (int s = 128; s > 0; s >>= 1){
        if (threadIdx.x < s) red[threadIdx.x] = max(red[threadIdx.x], red[threadIdx.x + s]);
        __syncthreads();
    }
    if (threadIdx.x == 0) out[b] = sqrtf(__uint_as_float(red[0]));
}

__global__ void k_resize(){
    int idx = blockIdx.x * blockDim.x + threadIdx.x;
    if (idx >= NPIX) return;
    int x = idx % IMG, y = (idx / IMG) % IMG, b = idx / (IMG*IMG);
    float fy = y * 0.125f - 0.4375f;
    float fx = x * 0.125f - 0.4375f;
    float fy0 = floorf(fy), fx0 = floorf(fx);
    float wy = fy - fy0, wx = fx - fx0;
    int y0 = max((int)fy0, 0), y1 = min((int)fy0 + 1, FHW-1);
    int x0 = max((int)fx0, 0), x1 = min((int)fx0 + 1, FHW-1);
    const unsigned int* mb = g_minbits + b*FHW*FHW;
    float s00 = sqrtf(__uint_as_float(mb[y0*FHW + x0]));
    float s01 = sqrtf(__uint_as_float(mb[y0*FHW + x1]));
    float s10 = sqrtf(__uint_as_float(mb[y1*FHW + x0]));
    float s11 = sqrtf(__uint_as_float(mb[y1*FHW + x1]));
    g_resized[idx] = (1.f-wy)*((1.f-wx)*s00 + wx*s01) + wy*((1.f-wx)*s10 + wx*s11);
}

__global__ void k_blurh(){
    __shared__ float w[17];
    if (threadIdx.x < 17) w[threadIdx.x] = g_gauss[threadIdx.x];
    __syncthreads();
    int idx = blockIdx.x * blockDim.x + threadIdx.x;
    if (idx >= NPIX) return;
    int x = idx % IMG, y = (idx / IMG) % IMG, b = idx / (IMG*IMG);
    const float* img = g_resized + b*IMG*IMG;
    float s = 0.f;
    #pragma unroll
    for (int t = 0; t < 17; t++){
        int yy = y - 8 + t;
        yy = (yy < 0) ? -yy : yy;
        yy = (yy > IMG-1) ? 2*(IMG-1) - yy : yy;
        s += w[t] * img[yy*IMG + x];
    }
    g_tmpb[idx] = s;
}

__global__ void k_blurv(float* __restrict__ out){
    __shared__ float w[17];
    if (threadIdx.x < 17) w[threadIdx.x] = g_gauss[threadIdx.x];
    __syncthreads();
    int idx = blockIdx.x * blockDim.x + threadIdx.x;
    if (idx >= NPIX) return;
    int x = idx % IMG, y = (idx / IMG) % IMG, b = idx / (IMG*IMG);
    const float* img = g_tmpb + b*IMG*IMG;
    float s = 0.f;
    #pragma unroll
    for (int t = 0; t < 17; t++){
        int xx = x - 8 + t;
        xx = (xx < 0) ? -xx : xx;
        xx = (xx > IMG-1) ? 2*(IMG-1) - xx : xx;
        s += w[t] * img[y*IMG + xx];
    }
    out[BIMG + idx] = s;
}

// ---------------------------------------------------------------------------
extern "C" void kernel_launch(void* const* d_in, const int* in_sizes, int n_in,
                              void* d_out, int out_size){
    const float* feat = (const float*)d_in[0];
    const float* mem  = (const float*)d_in[1];
    if (n_in >= 2 && in_sizes[0] == MMEM * CDIM){
        const float* t = feat; feat = mem; mem = t;
    }
    float* out = (float*)d_out;

    cudaFuncSetAttribute(k_gemm_tc, cudaFuncAttributeMaxDynamicSharedMemorySize, SMEM_TOTAL);

    k_init<<<(NFEAT + 255)/256, 256>>>();
    k_prep<<<NFEAT/8, 256>>>(feat, NFEAT, NFEAT, 0);
    k_prep<<<MPAD2/8, 256>>>(mem, MPAD2, MMEM, 1);

    dim3 g(NFEAT/MTILE, NTILES);   // 49 x 196, x fastest -> B tile L2 reuse
    k_gemm_tc<<<g, NTHREADS, SMEM_TOTAL>>>();

    k_scores<<<BIMG, 256>>>(out);
    int pb = (NPIX + 255)/256;
    k_resize<<<pb, 256>>>();
    k_blurh<<<pb, 256>>>();
    k_blurv<<<pb, 256>>>(out);
}

// round 13
// speedup vs baseline: 1.5498x; 1.5498x over previous
#include <cuda_runtime.h>
#include <cuda_bf16.h>
#include <cstdint>

#define NFEAT 6272
#define MMEM  50000
#define CDIM  1024
#define BIMG  8
#define FHW   28
#define IMG   224
#define NPIX  (BIMG*IMG*IMG)

#define MTILE 128
#define NTILE 128
#define NTILES 391
#define MPAD2 (NTILES*NTILE)     // 50048
#define KCH   64                 // bf16 elems per K chunk = 128B rows
#define NCHUNKS (CDIM/KCH)       // 16
#define NSTAGE 3

// smem rows: 128B data + 16B pad -> conflict-free ldmatrix (144 = 9*16)
#define ROWB   144
#define STAGEB (MTILE*ROWB)      // 18432 per operand per stage
#define AUX_OFF (2*NSTAGE*STAGEB)          // 110592
#define SMEM_TOTAL (AUX_OFF + 512*3)       // m2s, f2s, sred

// ---- static device scratch ----
__device__ float g_f2[NFEAT];
__device__ float g_m2[MPAD2];
__device__ unsigned int g_minbits[NFEAT];
__device__ float g_gauss[17];
__device__ float g_resized[NPIX];
__device__ float g_tmpb[NPIX];
__device__ __nv_bfloat16 g_featb[NFEAT*CDIM];
__device__ __nv_bfloat16 g_memb[(size_t)MPAD2*CDIM];

static __device__ __forceinline__ uint32_t smem_u32(const void* p){
    uint32_t a; asm("{ .reg .u64 t; cvta.to.shared.u64 t, %1; cvt.u32.u64 %0, t; }"
                    : "=r"(a) : "l"(p));
    return a;
}
static __device__ __forceinline__ void cp16(uint32_t dst, const void* src){
    asm volatile("cp.async.cg.shared.global [%0], [%1], 16;" :: "r"(dst), "l"(src) : "memory");
}
static __device__ __forceinline__ void ldsm4(uint32_t p, uint32_t &r0, uint32_t &r1,
                                             uint32_t &r2, uint32_t &r3){
    asm volatile("ldmatrix.sync.aligned.m8n8.x4.shared.b16 {%0,%1,%2,%3}, [%4];"
                 : "=r"(r0), "=r"(r1), "=r"(r2), "=r"(r3) : "r"(p));
}
static __device__ __forceinline__ void mma16816(float* c, uint32_t a0, uint32_t a1,
                                                uint32_t a2, uint32_t a3,
                                                uint32_t b0, uint32_t b1){
    asm volatile("mma.sync.aligned.m16n8k16.row.col.f32.bf16.bf16.f32 "
                 "{%0,%1,%2,%3},{%4,%5,%6,%7},{%8,%9},{%0,%1,%2,%3};"
                 : "+f"(c[0]), "+f"(c[1]), "+f"(c[2]), "+f"(c[3])
                 : "r"(a0), "r"(a1), "r"(a2), "r"(a3), "r"(b0), "r"(b1));
}

// ---------------------------------------------------------------------------
__global__ void k_init(){
    int tid = blockIdx.x * blockDim.x + threadIdx.x;
    if (tid < NFEAT) g_minbits[tid] = 0x7F7FFFFFu;
    if (tid < 17){
        float s = 0.f;
        #pragma unroll
        for (int t = 0; t < 17; t++){ float d = (float)t - 8.f; s += expf(-(d*d)/32.f); }
        float d = (float)tid - 8.f;
        g_gauss[tid] = expf(-(d*d)/32.f) / s;
    }
}

// ---------------------------------------------------------------------------
// fused fp32->bf16 conversion + squared row norm. one warp per row.
// ---------------------------------------------------------------------------
__global__ void k_prep(const float* __restrict__ X, int nrows, int nvalid, int mode){
    int warp = (blockIdx.x * blockDim.x + threadIdx.x) >> 5;
    int lane = threadIdx.x & 31;
    if (warp >= nrows) return;
    __nv_bfloat16* dst = (mode == 0 ? g_featb : g_memb) + (size_t)warp * CDIM;
    if (warp >= nvalid){
        uint2 z = make_uint2(0u, 0u);
        #pragma unroll
        for (int j = 0; j < 8; j++) ((uint2*)dst)[j*32 + lane] = z;
        if (lane == 0) g_m2[warp] = __int_as_float(0x7F800000);
        return;
    }
    const float4* src = (const float4*)(X + (size_t)warp * CDIM);
    float s = 0.f;
    #pragma unroll
    for (int j = 0; j < 8; j++){
        float4 v = src[j*32 + lane];
        s += v.x*v.x + v.y*v.y + v.z*v.z + v.w*v.w;
        __nv_bfloat162 p0 = __floats2bfloat162_rn(v.x, v.y);
        __nv_bfloat162 p1 = __floats2bfloat162_rn(v.z, v.w);
        uint2 o; o.x = *(uint32_t*)&p0; o.y = *(uint32_t*)&p1;
        ((uint2*)dst)[j*32 + lane] = o;
    }
    #pragma unroll
    for (int o = 16; o > 0; o >>= 1) s += __shfl_xor_sync(0xFFFFFFFFu, s, o);
    if (lane == 0){ if (mode == 0) g_f2[warp] = s; else g_m2[warp] = s; }
}

// ---------------------------------------------------------------------------
// bf16 HMMA distance GEMM + min epilogue.
// CTA 128x128, 8 warps (2M x 4N), warp tile 64x32, 2 CTAs/SM.
// KCH=64: 16 barrier regions, 4 k16 steps / region, fragment ping-pong,
// 3-stage smem ring, wait_group 0 at region top (prefetch lead = 1 chunk).
// ---------------------------------------------------------------------------
__global__ __launch_bounds__(256, 2)
void k_gemm_tc(){
    extern __shared__ char smraw[];
    const uint32_t sbase = smem_u32(smraw);
    const int tid = threadIdx.x;
    const int wid = tid >> 5, lane = tid & 31;
    const int warpM = wid >> 2, warpN = wid & 3;
    const int rowBase = blockIdx.x * MTILE;
    const int colBase = blockIdx.y * NTILE;

    float* m2s = (float*)(smraw + AUX_OFF);
    float* f2s = (float*)(smraw + AUX_OFF + 512);
    unsigned int* sred = (unsigned int*)(smraw + AUX_OFF + 1024);
    if (tid < 128){
        m2s[tid] = g_m2[colBase + tid];
        f2s[tid] = g_f2[rowBase + tid];
        sred[tid] = 0x7F7FFFFFu;
    }

    // ---- per-thread cp.async endpoints: rows r0+32t (t=0..3) of A and B ----
    const int r0 = tid >> 3, seg = tid & 7;
    const char* aSrc = (const char*)g_featb + ((size_t)(rowBase + r0))*(CDIM*2) + seg*16;
    const char* bSrc = (const char*)g_memb  + ((size_t)(colBase + r0))*(CDIM*2) + seg*16;
    const uint32_t aDst = sbase + r0*ROWB + seg*16;
    const uint32_t bDst = aDst + NSTAGE*STAGEB;

    #define ISSUE(ks, st) do { \
        const size_t _ko = (size_t)(ks) * (KCH*2); \
        const uint32_t _so = (uint32_t)((st) * STAGEB); \
        _Pragma("unroll") \
        for (int t = 0; t < 4; t++){ \
            cp16(aDst + _so + t*(32*ROWB), aSrc + _ko + (size_t)t*(32*CDIM*2)); \
            cp16(bDst + _so + t*(32*ROWB), bSrc + _ko + (size_t)t*(32*CDIM*2)); \
        } \
        asm volatile("cp.async.commit_group;" ::: "memory"); \
    } while(0)

    // ---- LDSM base offsets (k16 step s -> +32*s bytes within the 128B row) ----
    const int lrow = lane & 15;
    const int lcol16 = (lane >> 4) & 1;
    const uint32_t aOff = sbase + (warpM*64 + lrow)*ROWB + lcol16*16;
    const uint32_t bOff = sbase + NSTAGE*STAGEB + (warpN*32 + lrow)*ROWB + lcol16*16;

    uint32_t fa[2][4][4], fb[2][2][4];
    #define LOAD_FRAGS(buf, ap, bp) do { \
        _Pragma("unroll") \
        for (int mi = 0; mi < 4; mi++) \
            ldsm4((ap) + mi*(16*ROWB), fa[buf][mi][0], fa[buf][mi][1], \
                  fa[buf][mi][2], fa[buf][mi][3]); \
        _Pragma("unroll") \
        for (int nh = 0; nh < 2; nh++) \
            ldsm4((bp) + nh*(16*ROWB), fb[buf][nh][0], fb[buf][nh][1], \
                  fb[buf][nh][2], fb[buf][nh][3]); \
    } while(0)

    #define MMA_STEP(buf) do { \
        _Pragma("unroll") \
        for (int mi = 0; mi < 4; mi++) \
            _Pragma("unroll") \
            for (int ni = 0; ni < 4; ni++){ \
                int nh = ni >> 1, od = ni & 1; \
                mma16816(acc[mi][ni], fa[buf][mi][0], fa[buf][mi][1], \
                         fa[buf][mi][2], fa[buf][mi][3], \
                         fb[buf][nh][od], fb[buf][nh][od + 2]); \
            } \
    } while(0)

    float acc[4][4][4];
    #pragma unroll
    for (int mi = 0; mi < 4; mi++)
        #pragma unroll
        for (int ni = 0; ni < 4; ni++)
            #pragma unroll
            for (int k = 0; k < 4; k++) acc[mi][ni][k] = 0.f;

    // prologue: chunks 0,1 in flight; both resident after wait
    ISSUE(0, 0); ISSUE(1, 1);
    asm volatile("cp.async.wait_group 0;" ::: "memory");
    __syncthreads();

    // preload fragments for (chunk 0, step 0) into buf 0
    LOAD_FRAGS(0, aOff, bOff);

    #pragma unroll
    for (int ks = 0; ks < NCHUNKS; ks++){
        const int st  = ks % NSTAGE;
        const int stn = (ks + 1) % NSTAGE;
        if (ks > 0){
            // all outstanding copies (incl. chunk ks+1, issued a chunk ago) done
            asm volatile("cp.async.wait_group 0;" ::: "memory");
            __syncthreads();
        }
        if (ks + 2 < NCHUNKS) ISSUE(ks + 2, (ks + 2) % NSTAGE);

        const uint32_t ao = aOff + (uint32_t)(st * STAGEB);
        const uint32_t bo = bOff + (uint32_t)(st * STAGEB);
        // 4 k16 steps with fragment ping-pong; cross-chunk preload at step 3
        LOAD_FRAGS(1, ao + 32, bo + 32);
        MMA_STEP(0);
        LOAD_FRAGS(0, ao + 64, bo + 64);
        MMA_STEP(1);
        LOAD_FRAGS(1, ao + 96, bo + 96);
        MMA_STEP(0);
        if (ks + 1 < NCHUNKS)
            LOAD_FRAGS(0, aOff + (uint32_t)(stn * STAGEB), bOff + (uint32_t)(stn * STAGEB));
        MMA_STEP(1);
    }
    #undef ISSUE
    #undef LOAD_FRAGS
    #undef MMA_STEP

    // ---- epilogue: d2 = f2 + m2 - 2*dot, min-reduce ----
    {
        const int q = lane >> 2;        // row-in-8 group
        const int ql = lane & 3;        // col pair selector
        float m2v[4][2], f2lo[4], f2hi[4];
        #pragma unroll
        for (int ni = 0; ni < 4; ni++){
            int c = warpN*32 + ni*8 + 2*ql;
            m2v[ni][0] = m2s[c];
            m2v[ni][1] = m2s[c + 1];
        }
        #pragma unroll
        for (int mi = 0; mi < 4; mi++){
            f2lo[mi] = f2s[warpM*64 + mi*16 + q];
            f2hi[mi] = f2s[warpM*64 + mi*16 + q + 8];
        }
        #pragma unroll
        for (int mi = 0; mi < 4; mi++){
            float vlo = __int_as_float(0x7F800000);
            float vhi = vlo;
            #pragma unroll
            for (int ni = 0; ni < 4; ni++){
                vlo = fminf(vlo, fminf(fmaf(-2.f, acc[mi][ni][0], f2lo[mi] + m2v[ni][0]),
                                       fmaf(-2.f, acc[mi][ni][1], f2lo[mi] + m2v[ni][1])));
                vhi = fminf(vhi, fminf(fmaf(-2.f, acc[mi][ni][2], f2hi[mi] + m2v[ni][0]),
                                       fmaf(-2.f, acc[mi][ni][3], f2hi[mi] + m2v[ni][1])));
            }
            #pragma unroll
            for (int o = 1; o < 4; o <<= 1){
                vlo = fminf(vlo, __shfl_xor_sync(0xFFFFFFFFu, vlo, o));
                vhi = fminf(vhi, __shfl_xor_sync(0xFFFFFFFFu, vhi, o));
            }
            if (ql == 0){
                int r = warpM*64 + mi*16 + q;
                atomicMin(&sred[r],     __float_as_uint(fmaxf(vlo, 0.f)));
                atomicMin(&sred[r + 8], __float_as_uint(fmaxf(vhi, 0.f)));
            }
        }
    }
    __syncthreads();
    if (tid < 128)
        atomicMin(&g_minbits[rowBase + tid], sred[tid]);
}

// ---------------------------------------------------------------------------
__global__ void k_scores(float* __restrict__ out){
    __shared__ unsigned int red[256];
    const int b = blockIdx.x;
    unsigned int mb = 0u;
    for (int i = threadIdx.x; i < FHW*FHW; i += 256)
        mb = max(mb, g_minbits[b*FHW*FHW + i]);
    red[threadIdx.x] = mb; __syncthreads();
    for (int s = 128; s > 0; s >>= 1){
        if (threadIdx.x < s) red[threadIdx.x] = max(red[threadIdx.x], red[threadIdx.x + s]);
        __syncthreads();
    }
    if (threadIdx.x == 0) out[b] = sqrtf(__uint_as_float(red[0]));
}

__global__ void k_resize(){
    int idx = blockIdx.x * blockDim.x + threadIdx.x;
    if (idx >= NPIX) return;
    int x = idx % IMG, y = (idx / IMG) % IMG, b = idx / (IMG*IMG);
    float fy = y * 0.125f - 0.4375f;
    float fx = x * 0.125f - 0.4375f;
    float fy0 = floorf(fy), fx0 = floorf(fx);
    float wy = fy - fy0, wx = fx - fx0;
    int y0 = max((int)fy0, 0), y1 = min((int)fy0 + 1, FHW-1);
    int x0 = max((int)fx0, 0), x1 = min((int)fx0 + 1, FHW-1);
    const unsigned int* mb = g_minbits + b*FHW*FHW;
    float s00 = sqrtf(__uint_as_float(mb[y0*FHW + x0]));
    float s01 = sqrtf(__uint_as_float(mb[y0*FHW + x1]));
    float s10 = sqrtf(__uint_as_float(mb[y1*FHW + x0]));
    float s11 = sqrtf(__uint_as_float(mb[y1*FHW + x1]));
    g_resized[idx] = (1.f-wy)*((1.f-wx)*s00 + wx*s01) + wy*((1.f-wx)*s10 + wx*s11);
}

__global__ void k_blurh(){
    __shared__ float w[17];
    if (threadIdx.x < 17) w[threadIdx.x] = g_gauss[threadIdx.x];
    __syncthreads();
    int idx = blockIdx.x * blockDim.x + threadIdx.x;
    if (idx >= NPIX) return;
    int x = idx % IMG, y = (idx / IMG) % IMG, b = idx / (IMG*IMG);
    const float* img = g_resized + b*IMG*IMG;
    float s = 0.f;
    #pragma unroll
    for (int t = 0; t < 17; t++){
        int yy = y - 8 + t;
        yy = (yy < 0) ? -yy : yy;
        yy = (yy > IMG-1) ? 2*(IMG-1) - yy : yy;
        s += w[t] * img[yy*IMG + x];
    }
    g_tmpb[idx] = s;
}

__global__ void k_blurv(float* __restrict__ out){
    __shared__ float w[17];
    if (threadIdx.x < 17) w[threadIdx.x] = g_gauss[threadIdx.x];
    __syncthreads();
    int idx = blockIdx.x * blockDim.x + threadIdx.x;
    if (idx >= NPIX) return;
    int x = idx % IMG, y = (idx / IMG) % IMG, b = idx / (IMG*IMG);
    const float* img = g_tmpb + b*IMG*IMG;
    float s = 0.f;
    #pragma unroll
    for (int t = 0; t < 17; t++){
        int xx = x - 8 + t;
        xx = (xx < 0) ? -xx : xx;
        xx = (xx > IMG-1) ? 2*(IMG-1) - xx : xx;
        s += w[t] * img[y*IMG + xx];
    }
    out[BIMG + idx] = s;
}

// ---------------------------------------------------------------------------
extern "C" void kernel_launch(void* const* d_in, const int* in_sizes, int n_in,
                              void* d_out, int out_size){
    const float* feat = (const float*)d_in[0];
    const float* mem  = (const float*)d_in[1];
    if (n_in >= 2 && in_sizes[0] == MMEM * CDIM){
        const float* t = feat; feat = mem; mem = t;
    }
    float* out = (float*)d_out;

    cudaFuncSetAttribute(k_gemm_tc, cudaFuncAttributeMaxDynamicSharedMemorySize, SMEM_TOTAL);

    k_init<<<(NFEAT + 255)/256, 256>>>();
    k_prep<<<NFEAT/8, 256>>>(feat, NFEAT, NFEAT, 0);
    k_prep<<<MPAD2/8, 256>>>(mem, MPAD2, MMEM, 1);

    dim3 g(NFEAT/MTILE, NTILES);   // 49 x 391, x fastest -> B tile L2 reuse
    k_gemm_tc<<<g, 256, SMEM_TOTAL>>>();

    k_scores<<<BIMG, 256>>>(out);
    int pb = (NPIX + 255)/256;
    k_resize<<<pb, 256>>>();
    k_blurh<<<pb, 256>>>();
    k_blurv<<<pb, 256>>>(out);
}

// round 15
// speedup vs baseline: 1.6356x; 1.0554x over previous
#include <cuda_runtime.h>
#include <cuda_fp16.h>
#include <cstdint>

#define NFEAT 6272
#define MMEM  50000
#define CDIM  1024
#define BIMG  8
#define FHW   28
#define IMG   224
#define NPIX  (BIMG*IMG*IMG)

#define MTILE 128
#define NTILE 128
#define NTILES 391
#define MPAD2 (NTILES*NTILE)     // 50048
#define KCH   64                 // f16 elems per K chunk = 128B rows
#define NCHUNKS (CDIM/KCH)       // 16
#define NSTAGE 3

// smem rows: 128B data + 16B pad -> conflict-free ldmatrix (144 = 9*16)
#define ROWB   144
#define STAGEB (MTILE*ROWB)      // 18432 per operand per stage
#define AUX_OFF (2*NSTAGE*STAGEB)          // 110592
#define SMEM_TOTAL (AUX_OFF + 512*3)       // m2s, f2s, sred

// ---- static device scratch ----
__device__ float g_f2[NFEAT];
__device__ float g_m2[MPAD2];
__device__ unsigned int g_minbits[NFEAT];
__device__ float g_gauss[17];
__device__ float g_resized[NPIX];
__device__ float g_tmpb[NPIX];
__device__ __half g_feath[NFEAT*CDIM];
__device__ __half g_memh[(size_t)MPAD2*CDIM];

static __device__ __forceinline__ uint32_t smem_u32(const void* p){
    uint32_t a; asm("{ .reg .u64 t; cvta.to.shared.u64 t, %1; cvt.u32.u64 %0, t; }"
                    : "=r"(a) : "l"(p));
    return a;
}
static __device__ __forceinline__ void cp16(uint32_t dst, const void* src){
    asm volatile("cp.async.cg.shared.global [%0], [%1], 16;" :: "r"(dst), "l"(src) : "memory");
}
static __device__ __forceinline__ void ldsm4(uint32_t p, uint32_t &r0, uint32_t &r1,
                                             uint32_t &r2, uint32_t &r3){
    asm volatile("ldmatrix.sync.aligned.m8n8.x4.shared.b16 {%0,%1,%2,%3}, [%4];"
                 : "=r"(r0), "=r"(r1), "=r"(r2), "=r"(r3) : "r"(p));
}
// f16 x f16 -> f16 accumulate (2x32b packed accumulators)
static __device__ __forceinline__ void mma_f16(uint32_t* c, uint32_t a0, uint32_t a1,
                                               uint32_t a2, uint32_t a3,
                                               uint32_t b0, uint32_t b1){
    asm volatile("mma.sync.aligned.m16n8k16.row.col.f16.f16.f16.f16 "
                 "{%0,%1},{%2,%3,%4,%5},{%6,%7},{%0,%1};"
                 : "+r"(c[0]), "+r"(c[1])
                 : "r"(a0), "r"(a1), "r"(a2), "r"(a3), "r"(b0), "r"(b1));
}

// ---------------------------------------------------------------------------
__global__ void k_init(){
    int tid = blockIdx.x * blockDim.x + threadIdx.x;
    if (tid < NFEAT) g_minbits[tid] = 0x7F7FFFFFu;
    if (tid < 17){
        float s = 0.f;
        #pragma unroll
        for (int t = 0; t < 17; t++){ float d = (float)t - 8.f; s += expf(-(d*d)/32.f); }
        float d = (float)tid - 8.f;
        g_gauss[tid] = expf(-(d*d)/32.f) / s;
    }
}

// ---------------------------------------------------------------------------
// fused fp32->f16 conversion + squared row norm (fp32). one warp per row.
// ---------------------------------------------------------------------------
__global__ void k_prep(const float* __restrict__ X, int nrows, int nvalid, int mode){
    int warp = (blockIdx.x * blockDim.x + threadIdx.x) >> 5;
    int lane = threadIdx.x & 31;
    if (warp >= nrows) return;
    __half* dst = (mode == 0 ? g_feath : g_memh) + (size_t)warp * CDIM;
    if (warp >= nvalid){
        uint2 z = make_uint2(0u, 0u);
        #pragma unroll
        for (int j = 0; j < 8; j++) ((uint2*)dst)[j*32 + lane] = z;
        if (lane == 0) g_m2[warp] = __int_as_float(0x7F800000);
        return;
    }
    const float4* src = (const float4*)(X + (size_t)warp * CDIM);
    float s = 0.f;
    #pragma unroll
    for (int j = 0; j < 8; j++){
        float4 v = src[j*32 + lane];
        s += v.x*v.x + v.y*v.y + v.z*v.z + v.w*v.w;
        __half2 p0 = __floats2half2_rn(v.x, v.y);
        __half2 p1 = __floats2half2_rn(v.z, v.w);
        uint2 o; o.x = *(uint32_t*)&p0; o.y = *(uint32_t*)&p1;
        ((uint2*)dst)[j*32 + lane] = o;
    }
    #pragma unroll
    for (int o = 16; o > 0; o >>= 1) s += __shfl_xor_sync(0xFFFFFFFFu, s, o);
    if (lane == 0){ if (mode == 0) g_f2[warp] = s; else g_m2[warp] = s; }
}

// ---------------------------------------------------------------------------
// f16 HMMA distance GEMM + min epilogue.
// CTA 128x128, 8 warps (2M x 4N), warp tile 64x32, 2 CTAs/SM.
// KCH=64: 16 barrier regions, 4 k16 steps/region, fragment ping-pong,
// 3-stage smem ring, wait_group 1 at region top.
// ---------------------------------------------------------------------------
__global__ __launch_bounds__(256, 2)
void k_gemm_tc(){
    extern __shared__ char smraw[];
    const uint32_t sbase = smem_u32(smraw);
    const int tid = threadIdx.x;
    const int wid = tid >> 5, lane = tid & 31;
    const int warpM = wid >> 2, warpN = wid & 3;
    const int rowBase = blockIdx.x * MTILE;
    const int colBase = blockIdx.y * NTILE;

    float* m2s = (float*)(smraw + AUX_OFF);
    float* f2s = (float*)(smraw + AUX_OFF + 512);
    unsigned int* sred = (unsigned int*)(smraw + AUX_OFF + 1024);
    if (tid < 128){
        m2s[tid] = g_m2[colBase + tid];
        f2s[tid] = g_f2[rowBase + tid];
        sred[tid] = 0x7F7FFFFFu;
    }

    // ---- per-thread cp.async endpoints: rows r0+32t (t=0..3) of A and B ----
    const int r0 = tid >> 3, seg = tid & 7;
    const char* aSrc = (const char*)g_feath + ((size_t)(rowBase + r0))*(CDIM*2) + seg*16;
    const char* bSrc = (const char*)g_memh  + ((size_t)(colBase + r0))*(CDIM*2) + seg*16;
    const uint32_t aDst = sbase + r0*ROWB + seg*16;
    const uint32_t bDst = aDst + NSTAGE*STAGEB;

    #define ISSUE(ks, st) do { \
        const size_t _ko = (size_t)(ks) * (KCH*2); \
        const uint32_t _so = (uint32_t)((st) * STAGEB); \
        _Pragma("unroll") \
        for (int t = 0; t < 4; t++){ \
            cp16(aDst + _so + t*(32*ROWB), aSrc + _ko + (size_t)t*(32*CDIM*2)); \
            cp16(bDst + _so + t*(32*ROWB), bSrc + _ko + (size_t)t*(32*CDIM*2)); \
        } \
        asm volatile("cp.async.commit_group;" ::: "memory"); \
    } while(0)

    // ---- LDSM base offsets (k16 step s -> +32*s bytes within the 128B row) ----
    const int lrow = lane & 15;
    const int lcol16 = (lane >> 4) & 1;
    const uint32_t aOff = sbase + (warpM*64 + lrow)*ROWB + lcol16*16;
    const uint32_t bOff = sbase + NSTAGE*STAGEB + (warpN*32 + lrow)*ROWB + lcol16*16;

    uint32_t fa[2][4][4], fb[2][2][4];
    #define LOAD_FRAGS(buf, ap, bp) do { \
        _Pragma("unroll") \
        for (int mi = 0; mi < 4; mi++) \
            ldsm4((ap) + mi*(16*ROWB), fa[buf][mi][0], fa[buf][mi][1], \
                  fa[buf][mi][2], fa[buf][mi][3]); \
        _Pragma("unroll") \
        for (int nh = 0; nh < 2; nh++) \
            ldsm4((bp) + nh*(16*ROWB), fb[buf][nh][0], fb[buf][nh][1], \
                  fb[buf][nh][2], fb[buf][nh][3]); \
    } while(0)

    #define MMA_STEP(buf) do { \
        _Pragma("unroll") \
        for (int mi = 0; mi < 4; mi++) \
            _Pragma("unroll") \
            for (int ni = 0; ni < 4; ni++){ \
                int nh = ni >> 1, od = ni & 1; \
                mma_f16(acc[mi][ni], fa[buf][mi][0], fa[buf][mi][1], \
                        fa[buf][mi][2], fa[buf][mi][3], \
                        fb[buf][nh][od], fb[buf][nh][od + 2]); \
            } \
    } while(0)

    uint32_t acc[4][4][2];
    #pragma unroll
    for (int mi = 0; mi < 4; mi++)
        #pragma unroll
        for (int ni = 0; ni < 4; ni++){ acc[mi][ni][0] = 0u; acc[mi][ni][1] = 0u; }

    // prologue: chunks 0,1 in flight; chunk 0 resident after wait_group 1
    ISSUE(0, 0); ISSUE(1, 1);
    asm volatile("cp.async.wait_group 1;" ::: "memory");
    __syncthreads();

    // preload fragments for (chunk 0, step 0) into buf 0
    LOAD_FRAGS(0, aOff, bOff);

    #pragma unroll
    for (int ks = 0; ks < NCHUNKS; ks++){
        const int st  = ks % NSTAGE;
        const int stn = (ks + 1) % NSTAGE;
        if (ks > 0){
            // chunk ks (issued 2 regions ago) and ks+1 (1 region ago) must be
            // visible for this region's reads incl. the cross-chunk preload;
            // keep the freshest group (ks+2's predecessor) in flight.
            asm volatile("cp.async.wait_group 1;" ::: "memory");
            __syncthreads();
        }
        if (ks + 2 < NCHUNKS) ISSUE(ks + 2, (ks + 2) % NSTAGE);

        const uint32_t ao = aOff + (uint32_t)(st * STAGEB);
        const uint32_t bo = bOff + (uint32_t)(st * STAGEB);
        // 4 k16 steps with fragment ping-pong; cross-chunk preload at step 3
        LOAD_FRAGS(1, ao + 32, bo + 32);
        MMA_STEP(0);
        LOAD_FRAGS(0, ao + 64, bo + 64);
        MMA_STEP(1);
        LOAD_FRAGS(1, ao + 96, bo + 96);
        MMA_STEP(0);
        if (ks + 1 < NCHUNKS)
            LOAD_FRAGS(0, aOff + (uint32_t)(stn * STAGEB), bOff + (uint32_t)(stn * STAGEB));
        MMA_STEP(1);
    }
    #undef ISSUE
    #undef LOAD_FRAGS
    #undef MMA_STEP

    // ---- epilogue: d2 = f2 + m2 - 2*dot, min-reduce ----
    {
        const int q = lane >> 2;        // row-in-8 group
        const int ql = lane & 3;        // col pair selector
        float m2v[4][2], f2lo[4], f2hi[4];
        #pragma unroll
        for (int ni = 0; ni < 4; ni++){
            int c = warpN*32 + ni*8 + 2*ql;
            m2v[ni][0] = m2s[c];
            m2v[ni][1] = m2s[c + 1];
        }
        #pragma unroll
        for (int mi = 0; mi < 4; mi++){
            f2lo[mi] = f2s[warpM*64 + mi*16 + q];
            f2hi[mi] = f2s[warpM*64 + mi*16 + q + 8];
        }
        #pragma unroll
        for (int mi = 0; mi < 4; mi++){
            float vlo = __int_as_float(0x7F800000);
            float vhi = vlo;
            #pragma unroll
            for (int ni = 0; ni < 4; ni++){
                float2 p0 = __half22float2(*(__half2*)&acc[mi][ni][0]); // row q  : c0,c1
                float2 p1 = __half22float2(*(__half2*)&acc[mi][ni][1]); // row q+8: c2,c3
                vlo = fminf(vlo, fminf(fmaf(-2.f, p0.x, f2lo[mi] + m2v[ni][0]),
                                       fmaf(-2.f, p0.y, f2lo[mi] + m2v[ni][1])));
                vhi = fminf(vhi, fminf(fmaf(-2.f, p1.x, f2hi[mi] + m2v[ni][0]),
                                       fmaf(-2.f, p1.y, f2hi[mi] + m2v[ni][1])));
            }
            #pragma unroll
            for (int o = 1; o < 4; o <<= 1){
                vlo = fminf(vlo, __shfl_xor_sync(0xFFFFFFFFu, vlo, o));
                vhi = fminf(vhi, __shfl_xor_sync(0xFFFFFFFFu, vhi, o));
            }
            if (ql == 0){
                int r = warpM*64 + mi*16 + q;
                atomicMin(&sred[r],     __float_as_uint(fmaxf(vlo, 0.f)));
                atomicMin(&sred[r + 8], __float_as_uint(fmaxf(vhi, 0.f)));
            }
        }
    }
    __syncthreads();
    if (tid < 128)
        atomicMin(&g_minbits[rowBase + tid], sred[tid]);
}

// ---------------------------------------------------------------------------
__global__ void k_scores(float* __restrict__ out){
    __shared__ unsigned int red[256];
    const int b = blockIdx.x;
    unsigned int mb = 0u;
    for (int i = threadIdx.x; i < FHW*FHW; i += 256)
        mb = max(mb, g_minbits[b*FHW*FHW + i]);
    red[threadIdx.x] = mb; __syncthreads();
    for (int s = 128; s > 0; s >>= 1){
        if (threadIdx.x < s) red[threadIdx.x] = max(red[threadIdx.x], red[threadIdx.x + s]);
        __syncthreads();
    }
    if (threadIdx.x == 0) out[b] = sqrtf(__uint_as_float(red[0]));
}

__global__ void k_resize(){
    int idx = blockIdx.x * blockDim.x + threadIdx.x;
    if (idx >= NPIX) return;
    int x = idx % IMG, y = (idx / IMG) % IMG, b = idx / (IMG*IMG);
    float fy = y * 0.125f - 0.4375f;
    float fx = x * 0.125f - 0.4375f;
    float fy0 = floorf(fy), fx0 = floorf(fx);
    float wy = fy - fy0, wx = fx - fx0;
    int y0 = max((int)fy0, 0), y1 = min((int)fy0 + 1, FHW-1);
    int x0 = max((int)fx0, 0), x1 = min((int)fx0 + 1, FHW-1);
    const unsigned int* mb = g_minbits + b*FHW*FHW;
    float s00 = sqrtf(__uint_as_float(mb[y0*FHW + x0]));
    float s01 = sqrtf(__uint_as_float(mb[y0*FHW + x1]));
    float s10 = sqrtf(__uint_as_float(mb[y1*FHW + x0]));
    float s11 = sqrtf(__uint_as_float(mb[y1*FHW + x1]));
    g_resized[idx] = (1.f-wy)*((1.f-wx)*s00 + wx*s01) + wy*((1.f-wx)*s10 + wx*s11);
}

__global__ void k_blurh(){
    __shared__ float w[17];
    if (threadIdx.x < 17) w[threadIdx.x] = g_gauss[threadIdx.x];
    __syncthreads();
    int idx = blockIdx.x * blockDim.x + threadIdx.x;
    if (idx >= NPIX) return;
    int x = idx % IMG, y = (idx / IMG) % IMG, b = idx / (IMG*IMG);
    const float* img = g_resized + b*IMG*IMG;
    float s = 0.f;
    #pragma unroll
    for (int t = 0; t < 17; t++){
        int yy = y - 8 + t;
        yy = (yy < 0) ? -yy : yy;
        yy = (yy > IMG-1) ? 2*(IMG-1) - yy : yy;
        s += w[t] * img[yy*IMG + x];
    }
    g_tmpb[idx] = s;
}

__global__ void k_blurv(float* __restrict__ out){
    __shared__ float w[17];
    if (threadIdx.x < 17) w[threadIdx.x] = g_gauss[threadIdx.x];
    __syncthreads();
    int idx = blockIdx.x * blockDim.x + threadIdx.x;
    if (idx >= NPIX) return;
    int x = idx % IMG, y = (idx / IMG) % IMG, b = idx / (IMG*IMG);
    const float* img = g_tmpb + b*IMG*IMG;
    float s = 0.f;
    #pragma unroll
    for (int t = 0; t < 17; t++){
        int xx = x - 8 + t;
        xx = (xx < 0) ? -xx : xx;
        xx = (xx > IMG-1) ? 2*(IMG-1) - xx : xx;
        s += w[t] * img[y*IMG + xx];
    }
    out[BIMG + idx] = s;
}

// ---------------------------------------------------------------------------
extern "C" void kernel_launch(void* const* d_in, const int* in_sizes, int n_in,
                              void* d_out, int out_size){
    const float* feat = (const float*)d_in[0];
    const float* mem  = (const float*)d_in[1];
    if (n_in >= 2 && in_sizes[0] == MMEM * CDIM){
        const float* t = feat; feat = mem; mem = t;
    }
    float* out = (float*)d_out;

    cudaFuncSetAttribute(k_gemm_tc, cudaFuncAttributeMaxDynamicSharedMemorySize, SMEM_TOTAL);

    k_init<<<(NFEAT + 255)/256, 256>>>();
    k_prep<<<NFEAT/8, 256>>>(feat, NFEAT, NFEAT, 0);
    k_prep<<<MPAD2/8, 256>>>(mem, MPAD2, MMEM, 1);

    dim3 g(NFEAT/MTILE, NTILES);   // 49 x 391, x fastest -> B tile L2 reuse
    k_gemm_tc<<<g, 256, SMEM_TOTAL>>>();

    k_scores<<<BIMG, 256>>>(out);
    int pb = (NPIX + 255)/256;
    k_resize<<<pb, 256>>>();
    k_blurh<<<pb, 256>>>();
    k_blurv<<<pb, 256>>>(out);
}

// round 16
// speedup vs baseline: 1.9018x; 1.1627x over previous
#include <cuda_runtime.h>
#include <cuda_fp16.h>
#include <cstdint>

#define NFEAT 6272
#define MMEM  50000
#define CDIM  1024
#define BIMG  8
#define FHW   28
#define IMG   224
#define NPIX  (BIMG*IMG*IMG)

#define MTILE 128
#define NTILE 128
#define NTILES 391
#define MPAD2 (NTILES*NTILE)     // 50048
#define KCH   64                 // f16 elems per K chunk = 128B rows
#define NCHUNKS (CDIM/KCH)       // 16
#define NSTAGE 2

// SW128-swizzled 128B rows: no padding, conflict-free ldmatrix
#define ROWB   128
#define STAGEB (MTILE*ROWB)                // 16384 per operand per stage
#define SBBASE (NSTAGE*STAGEB)             // 32768
#define AUX_OFF (2*NSTAGE*STAGEB)          // 65536 (rel. to aligned base)
#define SMEM_TOTAL (1024 + AUX_OFF + 512*3)  // align slack + tiles + aux

// ---- static device scratch ----
__device__ float g_f2[NFEAT];
__device__ float g_m2[MPAD2];
__device__ unsigned int g_minbits[NFEAT];
__device__ float g_gauss[17];
__device__ float g_resized[NPIX];
__device__ float g_tmpb[NPIX];
__device__ __half g_feath[NFEAT*CDIM];
__device__ __half g_memh[(size_t)MPAD2*CDIM];

static __device__ __forceinline__ uint32_t smem_u32(const void* p){
    uint32_t a; asm("{ .reg .u64 t; cvta.to.shared.u64 t, %1; cvt.u32.u64 %0, t; }"
                    : "=r"(a) : "l"(p));
    return a;
}
static __device__ __forceinline__ void cp16(uint32_t dst, const void* src){
    asm volatile("cp.async.cg.shared.global [%0], [%1], 16;" :: "r"(dst), "l"(src) : "memory");
}
static __device__ __forceinline__ void ldsm4(uint32_t p, uint32_t &r0, uint32_t &r1,
                                             uint32_t &r2, uint32_t &r3){
    asm volatile("ldmatrix.sync.aligned.m8n8.x4.shared.b16 {%0,%1,%2,%3}, [%4];"
                 : "=r"(r0), "=r"(r1), "=r"(r2), "=r"(r3) : "r"(p));
}
// f16 x f16 -> f16 accumulate (2x32b packed accumulators)
static __device__ __forceinline__ void mma_f16(uint32_t* c, uint32_t a0, uint32_t a1,
                                               uint32_t a2, uint32_t a3,
                                               uint32_t b0, uint32_t b1){
    asm volatile("mma.sync.aligned.m16n8k16.row.col.f16.f16.f16.f16 "
                 "{%0,%1},{%2,%3,%4,%5},{%6,%7},{%0,%1};"
                 : "+r"(c[0]), "+r"(c[1])
                 : "r"(a0), "r"(a1), "r"(a2), "r"(a3), "r"(b0), "r"(b1));
}

// ---------------------------------------------------------------------------
__global__ void k_init(){
    int tid = blockIdx.x * blockDim.x + threadIdx.x;
    if (tid < NFEAT) g_minbits[tid] = 0x7F7FFFFFu;
    if (tid < 17){
        float s = 0.f;
        #pragma unroll
        for (int t = 0; t < 17; t++){ float d = (float)t - 8.f; s += expf(-(d*d)/32.f); }
        float d = (float)tid - 8.f;
        g_gauss[tid] = expf(-(d*d)/32.f) / s;
    }
}

// ---------------------------------------------------------------------------
// fused fp32->f16 conversion + squared row norm (fp32). one warp per row.
// ---------------------------------------------------------------------------
__global__ void k_prep(const float* __restrict__ X, int nrows, int nvalid, int mode){
    int warp = (blockIdx.x * blockDim.x + threadIdx.x) >> 5;
    int lane = threadIdx.x & 31;
    if (warp >= nrows) return;
    __half* dst = (mode == 0 ? g_feath : g_memh) + (size_t)warp * CDIM;
    if (warp >= nvalid){
        uint2 z = make_uint2(0u, 0u);
        #pragma unroll
        for (int j = 0; j < 8; j++) ((uint2*)dst)[j*32 + lane] = z;
        if (lane == 0) g_m2[warp] = __int_as_float(0x7F800000);
        return;
    }
    const float4* src = (const float4*)(X + (size_t)warp * CDIM);
    float s = 0.f;
    #pragma unroll
    for (int j = 0; j < 8; j++){
        float4 v = src[j*32 + lane];
        s += v.x*v.x + v.y*v.y + v.z*v.z + v.w*v.w;
        __half2 p0 = __floats2half2_rn(v.x, v.y);
        __half2 p1 = __floats2half2_rn(v.z, v.w);
        uint2 o; o.x = *(uint32_t*)&p0; o.y = *(uint32_t*)&p1;
        ((uint2*)dst)[j*32 + lane] = o;
    }
    #pragma unroll
    for (int o = 16; o > 0; o >>= 1) s += __shfl_xor_sync(0xFFFFFFFFu, s, o);
    if (lane == 0){ if (mode == 0) g_f2[warp] = s; else g_m2[warp] = s; }
}

// ---------------------------------------------------------------------------
// f16 HMMA distance GEMM + min epilogue.
// CTA 128x128, 8 warps (2M x 4N), warp tile 64x32, 3 CTAs/SM.
// KCH=64: 16 barrier regions, 4 k16 steps/region, fragment ping-pong,
// 2-stage SW128-swizzled smem ring, wait_group 0 at region top.
// ---------------------------------------------------------------------------
__global__ __launch_bounds__(256, 3)
void k_gemm_tc(){
    extern __shared__ char smraw[];
    const uint32_t rawb = smem_u32(smraw);
    const uint32_t sbase = (rawb + 1023u) & ~1023u;      // 1KB-align for swizzle
    char* smal = smraw + (sbase - rawb);
    const int tid = threadIdx.x;
    const int wid = tid >> 5, lane = tid & 31;
    const int warpM = wid >> 2, warpN = wid & 3;
    const int rowBase = blockIdx.x * MTILE;
    const int colBase = blockIdx.y * NTILE;

    float* m2s = (float*)(smal + AUX_OFF);
    float* f2s = (float*)(smal + AUX_OFF + 512);
    unsigned int* sred = (unsigned int*)(smal + AUX_OFF + 1024);
    if (tid < 128){
        m2s[tid] = g_m2[colBase + tid];
        f2s[tid] = g_f2[rowBase + tid];
        sred[tid] = 0x7F7FFFFFu;
    }

    // ---- per-thread cp.async endpoints: rows r0+32t (t=0..3), swizzled dst ----
    const int r0 = tid >> 3, seg = tid & 7;
    const char* aSrc = (const char*)g_feath + ((size_t)(rowBase + r0))*(CDIM*2) + seg*16;
    const char* bSrc = (const char*)g_memh  + ((size_t)(colBase + r0))*(CDIM*2) + seg*16;
    const uint32_t wsw = (uint32_t)((seg*16) ^ ((r0 & 7) << 4));   // (r0+32t)&7 == r0&7
    const uint32_t aDst = sbase + r0*ROWB + wsw;
    const uint32_t bDst = aDst + SBBASE;

    #define ISSUE(ks, st) do { \
        const size_t _ko = (size_t)(ks) * (KCH*2); \
        const uint32_t _so = (uint32_t)((st) * STAGEB); \
        _Pragma("unroll") \
        for (int t = 0; t < 4; t++){ \
            cp16(aDst + _so + t*(32*ROWB), aSrc + _ko + (size_t)t*(32*CDIM*2)); \
            cp16(bDst + _so + t*(32*ROWB), bSrc + _ko + (size_t)t*(32*CDIM*2)); \
        } \
        asm volatile("cp.async.commit_group;" ::: "memory"); \
    } while(0)

    // ---- LDSM row bases + per-step swizzled in-row offsets ----
    const int lrow = lane & 15;
    const int lcol16 = (lane >> 4) & 1;
    const uint32_t lsw = (uint32_t)((lrow & 7) << 4);   // row&7 invariant to mi*16
    const uint32_t o0 = (uint32_t)((0*32 + lcol16*16)) ^ lsw;
    const uint32_t o1 = (uint32_t)((1*32 + lcol16*16)) ^ lsw;
    const uint32_t o2 = (uint32_t)((2*32 + lcol16*16)) ^ lsw;
    const uint32_t o3 = (uint32_t)((3*32 + lcol16*16)) ^ lsw;
    const uint32_t aRow = sbase + (warpM*64 + lrow)*ROWB;
    const uint32_t bRow = sbase + SBBASE + (warpN*32 + lrow)*ROWB;

    uint32_t fa[2][4][4], fb[2][2][4];
    #define LOAD_FRAGS(buf, ap, bp) do { \
        _Pragma("unroll") \
        for (int mi = 0; mi < 4; mi++) \
            ldsm4((ap) + mi*(16*ROWB), fa[buf][mi][0], fa[buf][mi][1], \
                  fa[buf][mi][2], fa[buf][mi][3]); \
        _Pragma("unroll") \
        for (int nh = 0; nh < 2; nh++) \
            ldsm4((bp) + nh*(16*ROWB), fb[buf][nh][0], fb[buf][nh][1], \
                  fb[buf][nh][2], fb[buf][nh][3]); \
    } while(0)

    #define MMA_STEP(buf) do { \
        _Pragma("unroll") \
        for (int mi = 0; mi < 4; mi++) \
            _Pragma("unroll") \
            for (int ni = 0; ni < 4; ni++){ \
                int nh = ni >> 1, od = ni & 1; \
                mma_f16(acc[mi][ni], fa[buf][mi][0], fa[buf][mi][1], \
                        fa[buf][mi][2], fa[buf][mi][3], \
                        fb[buf][nh][od], fb[buf][nh][od + 2]); \
            } \
    } while(0)

    uint32_t acc[4][4][2];
    #pragma unroll
    for (int mi = 0; mi < 4; mi++)
        #pragma unroll
        for (int ni = 0; ni < 4; ni++){ acc[mi][ni][0] = 0u; acc[mi][ni][1] = 0u; }

    // prologue: chunk 0 in flight
    ISSUE(0, 0);
    asm volatile("cp.async.wait_group 0;" ::: "memory");
    __syncthreads();

    #pragma unroll
    for (int ks = 0; ks < NCHUNKS; ks++){
        const int st = ks & 1;
        if (ks > 0){
            asm volatile("cp.async.wait_group 0;" ::: "memory");
            __syncthreads();
        }
        if (ks + 1 < NCHUNKS) ISSUE(ks + 1, st ^ 1);

        const uint32_t ao = aRow + (uint32_t)(st * STAGEB);
        const uint32_t bo = bRow + (uint32_t)(st * STAGEB);
        // 4 k16 steps with fragment ping-pong (preload inside region)
        LOAD_FRAGS(0, ao + o0, bo + o0);
        LOAD_FRAGS(1, ao + o1, bo + o1);
        MMA_STEP(0);
        LOAD_FRAGS(0, ao + o2, bo + o2);
        MMA_STEP(1);
        LOAD_FRAGS(1, ao + o3, bo + o3);
        MMA_STEP(0);
        MMA_STEP(1);
    }
    #undef ISSUE
    #undef LOAD_FRAGS
    #undef MMA_STEP

    // ---- epilogue: d2 = f2 + m2 - 2*dot, min-reduce ----
    {
        const int q = lane >> 2;        // row-in-8 group
        const int ql = lane & 3;        // col pair selector
        float m2v[4][2], f2lo[4], f2hi[4];
        #pragma unroll
        for (int ni = 0; ni < 4; ni++){
            int c = warpN*32 + ni*8 + 2*ql;
            m2v[ni][0] = m2s[c];
            m2v[ni][1] = m2s[c + 1];
        }
        #pragma unroll
        for (int mi = 0; mi < 4; mi++){
            f2lo[mi] = f2s[warpM*64 + mi*16 + q];
            f2hi[mi] = f2s[warpM*64 + mi*16 + q + 8];
        }
        #pragma unroll
        for (int mi = 0; mi < 4; mi++){
            float vlo = __int_as_float(0x7F800000);
            float vhi = vlo;
            #pragma unroll
            for (int ni = 0; ni < 4; ni++){
                float2 p0 = __half22float2(*(__half2*)&acc[mi][ni][0]); // row q  : c0,c1
                float2 p1 = __half22float2(*(__half2*)&acc[mi][ni][1]); // row q+8: c2,c3
                vlo = fminf(vlo, fminf(fmaf(-2.f, p0.x, f2lo[mi] + m2v[ni][0]),
                                       fmaf(-2.f, p0.y, f2lo[mi] + m2v[ni][1])));
                vhi = fminf(vhi, fminf(fmaf(-2.f, p1.x, f2hi[mi] + m2v[ni][0]),
                                       fmaf(-2.f, p1.y, f2hi[mi] + m2v[ni][1])));
            }
            #pragma unroll
            for (int o = 1; o < 4; o <<= 1){
                vlo = fminf(vlo, __shfl_xor_sync(0xFFFFFFFFu, vlo, o));
                vhi = fminf(vhi, __shfl_xor_sync(0xFFFFFFFFu, vhi, o));
            }
            if (ql == 0){
                int r = warpM*64 + mi*16 + q;
                atomicMin(&sred[r],     __float_as_uint(fmaxf(vlo, 0.f)));
                atomicMin(&sred[r + 8], __float_as_uint(fmaxf(vhi, 0.f)));
            }
        }
    }
    __syncthreads();
    if (tid < 128)
        atomicMin(&g_minbits[rowBase + tid], sred[tid]);
}

// ---------------------------------------------------------------------------
__global__ void k_scores(float* __restrict__ out){
    __shared__ unsigned int red[256];
    const int b = blockIdx.x;
    unsigned int mb = 0u;
    for (int i = threadIdx.x; i < FHW*FHW; i += 256)
        mb = max(mb, g_minbits[b*FHW*FHW + i]);
    red[threadIdx.x] = mb; __syncthreads();
    for (int s = 128; s > 0; s >>= 1){
        if (threadIdx.x < s) red[threadIdx.x] = max(red[threadIdx.x], red[threadIdx.x + s]);
        __syncthreads();
    }
    if (threadIdx.x == 0) out[b] = sqrtf(__uint_as_float(red[0]));
}

__global__ void k_resize(){
    int idx = blockIdx.x * blockDim.x + threadIdx.x;
    if (idx >= NPIX) return;
    int x = idx % IMG, y = (idx / IMG) % IMG, b = idx / (IMG*IMG);
    float fy = y * 0.125f - 0.4375f;
    float fx = x * 0.125f - 0.4375f;
    float fy0 = floorf(fy), fx0 = floorf(fx);
    float wy = fy - fy0, wx = fx - fx0;
    int y0 = max((int)fy0, 0), y1 = min((int)fy0 + 1, FHW-1);
    int x0 = max((int)fx0, 0), x1 = min((int)fx0 + 1, FHW-1);
    const unsigned int* mb = g_minbits + b*FHW*FHW;
    float s00 = sqrtf(__uint_as_float(mb[y0*FHW + x0]));
    float s01 = sqrtf(__uint_as_float(mb[y0*FHW + x1]));
    float s10 = sqrtf(__uint_as_float(mb[y1*FHW + x0]));
    float s11 = sqrtf(__uint_as_float(mb[y1*FHW + x1]));
    g_resized[idx] = (1.f-wy)*((1.f-wx)*s00 + wx*s01) + wy*((1.f-wx)*s10 + wx*s11);
}

__global__ void k_blurh(){
    __shared__ float w[17];
    if (threadIdx.x < 17) w[threadIdx.x] = g_gauss[threadIdx.x];
    __syncthreads();
    int idx = blockIdx.x * blockDim.x + threadIdx.x;
    if (idx >= NPIX) return;
    int x = idx % IMG, y = (idx / IMG) % IMG, b = idx / (IMG*IMG);
    const float* img = g_resized + b*IMG*IMG;
    float s = 0.f;
    #pragma unroll
    for (int t = 0; t < 17; t++){
        int yy = y - 8 + t;
        yy = (yy < 0) ? -yy : yy;
        yy = (yy > IMG-1) ? 2*(IMG-1) - yy : yy;
        s += w[t] * img[yy*IMG + x];
    }
    g_tmpb[idx] = s;
}

__global__ void k_blurv(float* __restrict__ out){
    __shared__ float w[17];
    if (threadIdx.x < 17) w[threadIdx.x] = g_gauss[threadIdx.x];
    __syncthreads();
    int idx = blockIdx.x * blockDim.x + threadIdx.x;
    if (idx >= NPIX) return;
    int x = idx % IMG, y = (idx / IMG) % IMG, b = idx / (IMG*IMG);
    const float* img = g_tmpb + b*IMG*IMG;
    float s = 0.f;
    #pragma unroll
    for (int t = 0; t < 17; t++){
        int xx = x - 8 + t;
        xx = (xx < 0) ? -xx : xx;
        xx = (xx > IMG-1) ? 2*(IMG-1) - xx : xx;
        s += w[t] * img[y*IMG + xx];
    }
    out[BIMG + idx] = s;
}

// ---------------------------------------------------------------------------
extern "C" void kernel_launch(void* const* d_in, const int* in_sizes, int n_in,
                              void* d_out, int out_size){
    const float* feat = (const float*)d_in[0];
    const float* mem  = (const float*)d_in[1];
    if (n_in >= 2 && in_sizes[0] == MMEM * CDIM){
        const float* t = feat; feat = mem; mem = t;
    }
    float* out = (float*)d_out;

    cudaFuncSetAttribute(k_gemm_tc, cudaFuncAttributeMaxDynamicSharedMemorySize, SMEM_TOTAL);

    k_init<<<(NFEAT + 255)/256, 256>>>();
    k_prep<<<NFEAT/8, 256>>>(feat, NFEAT, NFEAT, 0);
    k_prep<<<MPAD2/8, 256>>>(mem, MPAD2, MMEM, 1);

    dim3 g(NFEAT/MTILE, NTILES);   // 49 x 391, x fastest -> B tile L2 reuse
    k_gemm_tc<<<g, 256, SMEM_TOTAL>>>();

    k_scores<<<BIMG, 256>>>(out);
    int pb = (NPIX + 255)/256;
    k_resize<<<pb, 256>>>();
    k_blurh<<<pb, 256>>>();
    k_blurv<<<pb, 256>>>(out);
}